// round 4
// baseline (speedup 1.0000x reference)
#include <cuda_runtime.h>
#include <cuda_fp16.h>
#include <math.h>

// ---------------- scratch (no allocation allowed) ----------------
__device__ __half g_hs[5000000];   // 50000 x 100, fp16
__device__ float  g_acc0[5000000];
__device__ float  g_dinv[50048];
__device__ int    g_cnt[50048];
__device__ int    g_rowptr[50049];
__device__ int    g_off[50049];
__device__ int    g_adj[800064];
__device__ int    g_bsum[256];
__device__ float  g_partials[512];
__device__ float  g_norm2;

// ---------------- prep: zero counters + ||x||^2 partial sums ----------------
__global__ void prep_kernel(const float* __restrict__ x, long n, int N) {
    int gs = gridDim.x * blockDim.x;
    for (int i = blockIdx.x * blockDim.x + threadIdx.x; i < N; i += gs) g_cnt[i] = 0;
    float s = 0.f;
    for (long i = (long)blockIdx.x * blockDim.x + threadIdx.x; i < n; i += gs) {
        float v = x[i];
        s += v * v;
    }
    __shared__ float sm[256];
    sm[threadIdx.x] = s;
    __syncthreads();
    for (int o = 128; o > 0; o >>= 1) {
        if (threadIdx.x < o) sm[threadIdx.x] += sm[threadIdx.x + o];
        __syncthreads();
    }
    if (threadIdx.x == 0) g_partials[blockIdx.x] = sm[0];
}

// ---------------- CSR build ----------------
__global__ void hist_kernel(const int* __restrict__ dst, int E) {
    int i = blockIdx.x * blockDim.x + threadIdx.x;
    if (i < E) atomicAdd(&g_cnt[dst[i]], 1);
}

__global__ void scan1_kernel(int N) {
    __shared__ int sm[256];
    int node = blockIdx.x * 256 + threadIdx.x;
    int c = (node < N) ? g_cnt[node] : 0;
    sm[threadIdx.x] = c;
    __syncthreads();
    for (int o = 1; o < 256; o <<= 1) {
        int v = (threadIdx.x >= o) ? sm[threadIdx.x - o] : 0;
        __syncthreads();
        sm[threadIdx.x] += v;
        __syncthreads();
    }
    if (node <= N) g_rowptr[node] = sm[threadIdx.x] - c;
    if (threadIdx.x == 255) g_bsum[blockIdx.x] = sm[255];
}

__global__ void scan2_kernel(int nb) {
    __shared__ int sm[256];
    int c = (threadIdx.x < nb) ? g_bsum[threadIdx.x] : 0;
    sm[threadIdx.x] = c;
    __syncthreads();
    for (int o = 1; o < 256; o <<= 1) {
        int v = (threadIdx.x >= o) ? sm[threadIdx.x - o] : 0;
        __syncthreads();
        sm[threadIdx.x] += v;
        __syncthreads();
    }
    g_bsum[threadIdx.x] = sm[threadIdx.x] - c;
}

// scan3 also finalizes norm2 (block 0)
__global__ void scan3_kernel(int N, int E) {
    if (blockIdx.x == 0) {
        __shared__ float fm[256];
        fm[threadIdx.x] = g_partials[threadIdx.x] + g_partials[threadIdx.x + 256];
        __syncthreads();
        for (int o = 128; o > 0; o >>= 1) {
            if (threadIdx.x < o) fm[threadIdx.x] += fm[threadIdx.x + o];
            __syncthreads();
        }
        if (threadIdx.x == 0) g_norm2 = fm[0];
    }
    int node = blockIdx.x * 256 + threadIdx.x;
    if (node < N) {
        int r = g_rowptr[node] + g_bsum[blockIdx.x];
        g_rowptr[node] = r;
        g_off[node] = r;
        g_dinv[node] = rsqrtf((float)(g_cnt[node] + 1));  // +1 self-loop
    } else if (node == N) {
        g_rowptr[N] = E;
    }
}

__global__ void fill_kernel(const int* __restrict__ src, const int* __restrict__ dst, int E) {
    int i = blockIdx.x * blockDim.x + threadIdx.x;
    if (i < E) {
        int pos = atomicAdd(&g_off[dst[i]], 1);
        g_adj[pos] = src[i];
    }
}

// ---------------- GEMM: hs = fp16( rowscale * ((X + bin) @ W) ) ----------------
// rowscale = dinv[row] if scale_dinv else 1
// 128 rows/block, 256 threads: (tx: 25-col group, ty: rows ty & ty+64)
__global__ void __launch_bounds__(256)
gemm_kernel(const float* __restrict__ X, const float* __restrict__ W,
            const float* __restrict__ bin, int scale_dinv,
            __half* __restrict__ hs, int N) {
    extern __shared__ float smem[];
    float* sW = smem;          // 10000 floats
    float* sX = smem + 10000;  // 128*100 = 12800 floats
    int tid = threadIdx.x;
    int row0 = blockIdx.x * 128;

    for (int i = tid; i < 2500; i += 256)
        ((float4*)sW)[i] = __ldg((const float4*)W + i);
    for (int i = tid; i < 3200; i += 256) {
        int r = i / 25, c = i - r * 25;
        int gr = row0 + r;
        float4 v = make_float4(0.f, 0.f, 0.f, 0.f);
        if (gr < N) {
            v = __ldg((const float4*)(X + (size_t)gr * 100) + c);
            if (bin) {
                float4 b = __ldg((const float4*)bin + c);
                v.x += b.x; v.y += b.y; v.z += b.z; v.w += b.w;
            }
        }
        *((float4*)(sX + r * 100) + c) = v;
    }
    __syncthreads();

    int tx = tid & 3, ty = tid >> 2;
    float a0[25], a1[25];
#pragma unroll
    for (int c = 0; c < 25; c++) { a0[c] = 0.f; a1[c] = 0.f; }
    const float* x0p = sX + ty * 100;
    const float* x1p = sX + (ty + 64) * 100;
    const float* wcol = sW + tx * 25;
#pragma unroll 2
    for (int k = 0; k < 100; k++) {
        float x0 = x0p[k];
        float x1 = x1p[k];
        const float* wr = wcol + k * 100;
#pragma unroll
        for (int c = 0; c < 25; c++) {
            float w = wr[c];
            a0[c] += x0 * w;
            a1[c] += x1 * w;
        }
    }

    int gr0 = row0 + ty;
    int gr1 = row0 + ty + 64;
    if (gr0 < N) {
        float s = scale_dinv ? g_dinv[gr0] : 1.0f;
        __half* p = hs + (size_t)gr0 * 100 + tx * 25;
#pragma unroll
        for (int c = 0; c < 25; c++) p[c] = __float2half_rn(a0[c] * s);
    }
    if (gr1 < N) {
        float s = scale_dinv ? g_dinv[gr1] : 1.0f;
        __half* p = hs + (size_t)gr1 * 100 + tx * 25;
#pragma unroll
        for (int c = 0; c < 25; c++) p[c] = __float2half_rn(a1[c] * s);
    }
}

// ---------------- agg0: acc[i] = (dinv_i/nm) * sum_{j in N(i)+i} dinv_j*hs[j] ----------------
// warp/node; smem-staged indices; unroll-4 gather for MLP
__global__ void __launch_bounds__(256)
agg_kernel(const __half* __restrict__ hs, float* __restrict__ acc,
           const int* __restrict__ rowptr, const int* __restrict__ adj, int N) {
    __shared__ int   s_idx[8][32];
    __shared__ float s_dj[8][32];
    int w = threadIdx.x >> 5, lane = threadIdx.x & 31;
    int node = blockIdx.x * 8 + w;
    if (node >= N) return;
    float di = g_dinv[node];
    bool act = lane < 25;

    float4 sum = make_float4(0.f, 0.f, 0.f, 0.f);
    if (act) {
        uint2 raw = __ldg((const uint2*)(hs + (size_t)node * 100) + lane);
        float2 f0 = __half22float2(*(const __half2*)&raw.x);
        float2 f1 = __half22float2(*(const __half2*)&raw.y);
        sum.x = di * f0.x; sum.y = di * f0.y;
        sum.z = di * f1.x; sum.w = di * f1.y;
    }

    int beg = rowptr[node];
    int end = rowptr[node + 1];
    for (int base = beg; base < end; base += 32) {
        int idx = base + lane;
        int mi = 0; float dj = 0.f;
        if (idx < end) {
            mi = __ldg(adj + idx);
            dj = g_dinv[mi];
        }
        s_idx[w][lane] = mi;
        s_dj[w][lane] = dj;
        __syncwarp();
        int cnt = min(32, end - base);
#pragma unroll 4
        for (int j = 0; j < cnt; j++) {
            int sj = s_idx[w][j];
            float d = s_dj[w][j];
            if (act) {
                uint2 raw = __ldg((const uint2*)(hs + (size_t)sj * 100) + lane);
                float2 f0 = __half22float2(*(const __half2*)&raw.x);
                float2 f1 = __half22float2(*(const __half2*)&raw.y);
                sum.x += d * f0.x; sum.y += d * f0.y;
                sum.z += d * f1.x; sum.w += d * f1.y;
            }
        }
        __syncwarp();
    }

    if (act) {
        float os = di * rsqrtf(g_norm2);
        sum.x *= os; sum.y *= os; sum.z *= os; sum.w *= os;
        *((float4*)(acc + (size_t)node * 100) + lane) = sum;
    }
}

// ---------------- fused agg1 + MLP head ----------------
// hs already scaled by dinv_j. x2 = dinv_i * sum(hs[j]) + cb1; out = relu(x2@W0+b0)@W1+b1
__global__ void __launch_bounds__(256)
agg_head_kernel(const __half* __restrict__ hs, const float* __restrict__ cb1,
                const float* __restrict__ W0, const float* __restrict__ b0,
                const float* __restrict__ W1, const float* __restrict__ b1,
                float* __restrict__ out,
                const int* __restrict__ rowptr, const int* __restrict__ adj, int N) {
    __shared__ int s_idx[8][32];
    int w = threadIdx.x >> 5, lane = threadIdx.x & 31;
    int node = blockIdx.x * 8 + w;
    if (node >= N) return;
    bool act = lane < 25;
    int k0 = lane * 4;

    // preload weights into registers
    float w0r[40];
#pragma unroll
    for (int m = 0; m < 4; m++)
#pragma unroll
        for (int j = 0; j < 10; j++)
            w0r[m * 10 + j] = act ? __ldg(W0 + (k0 + m) * 10 + j) : 0.f;
    float4 bc = make_float4(0.f, 0.f, 0.f, 0.f);
    if (act) bc = __ldg((const float4*)cb1 + lane);
    float b0r[10], w1r[10];
#pragma unroll
    for (int j = 0; j < 10; j++) { b0r[j] = __ldg(b0 + j); w1r[j] = __ldg(W1 + j); }
    float b1v = __ldg(b1);

    float di = g_dinv[node];
    float4 sum = make_float4(0.f, 0.f, 0.f, 0.f);
    if (act) {
        uint2 raw = __ldg((const uint2*)(hs + (size_t)node * 100) + lane);
        float2 f0 = __half22float2(*(const __half2*)&raw.x);
        float2 f1 = __half22float2(*(const __half2*)&raw.y);
        sum.x = f0.x; sum.y = f0.y; sum.z = f1.x; sum.w = f1.y;
    }

    int beg = rowptr[node];
    int end = rowptr[node + 1];
    for (int base = beg; base < end; base += 32) {
        int idx = base + lane;
        s_idx[w][lane] = (idx < end) ? __ldg(adj + idx) : 0;
        __syncwarp();
        int cnt = min(32, end - base);
#pragma unroll 4
        for (int j = 0; j < cnt; j++) {
            int sj = s_idx[w][j];
            if (act) {
                uint2 raw = __ldg((const uint2*)(hs + (size_t)sj * 100) + lane);
                float2 f0 = __half22float2(*(const __half2*)&raw.x);
                float2 f1 = __half22float2(*(const __half2*)&raw.y);
                sum.x += f0.x; sum.y += f0.y; sum.z += f1.x; sum.w += f1.y;
            }
        }
        __syncwarp();
    }

    // x2 (4 features per active lane)
    float4 x2 = make_float4(0.f, 0.f, 0.f, 0.f);
    if (act) {
        x2.x = di * sum.x + bc.x;
        x2.y = di * sum.y + bc.y;
        x2.z = di * sum.z + bc.z;
        x2.w = di * sum.w + bc.w;
    }
    float p[10];
#pragma unroll
    for (int j = 0; j < 10; j++)
        p[j] = x2.x * w0r[j] + x2.y * w0r[10 + j] + x2.z * w0r[20 + j] + x2.w * w0r[30 + j];
    // warp reduction (lanes >=25 contribute 0)
#pragma unroll
    for (int j = 0; j < 10; j++) {
        float v = p[j];
        v += __shfl_down_sync(0xffffffffu, v, 16);
        v += __shfl_down_sync(0xffffffffu, v, 8);
        v += __shfl_down_sync(0xffffffffu, v, 4);
        v += __shfl_down_sync(0xffffffffu, v, 2);
        v += __shfl_down_sync(0xffffffffu, v, 1);
        p[j] = v;
    }
    if (lane == 0) {
        float o = b1v;
#pragma unroll
        for (int j = 0; j < 10; j++) o += fmaxf(p[j] + b0r[j], 0.f) * w1r[j];
        out[node] = o;
    }
}

extern "C" void kernel_launch(void* const* d_in, const int* in_sizes, int n_in,
                              void* d_out, int out_size) {
    const float* x   = (const float*)d_in[0];
    const int*   ei  = (const int*)d_in[1];
    const float* W0  = (const float*)d_in[2];
    const float* cb0 = (const float*)d_in[3];
    const float* W1  = (const float*)d_in[4];
    const float* cb1 = (const float*)d_in[5];
    const float* lW0 = (const float*)d_in[6];
    const float* lb0 = (const float*)d_in[7];
    const float* lW1 = (const float*)d_in[8];
    const float* lb1 = (const float*)d_in[9];
    float* out = (float*)d_out;

    int N = in_sizes[0] / 100;
    int E = in_sizes[1] / 2;
    const int* src = ei;
    const int* dst = ei + E;

    size_t gemm_smem = (10000 + 12800) * sizeof(float);  // 91.2 KB -> 2 blocks/SM
    cudaFuncSetAttribute(gemm_kernel,
                         cudaFuncAttributeMaxDynamicSharedMemorySize, (int)gemm_smem);

    __half* hs;
    float* acc0;
    int *rowptr, *adj;
    cudaGetSymbolAddress((void**)&hs, g_hs);
    cudaGetSymbolAddress((void**)&acc0, g_acc0);
    cudaGetSymbolAddress((void**)&rowptr, g_rowptr);
    cudaGetSymbolAddress((void**)&adj, g_adj);

    cudaStream_t s2;
    cudaStreamCreateWithFlags(&s2, cudaStreamNonBlocking);
    cudaEvent_t ev0, ev1;
    cudaEventCreateWithFlags(&ev0, cudaEventDisableTiming);
    cudaEventCreateWithFlags(&ev1, cudaEventDisableTiming);

    cudaEventRecord(ev0, 0);
    cudaStreamWaitEvent(s2, ev0, 0);

    // ----- branch A: norm + CSR build -----
    long n_elem = (long)N * 100;
    prep_kernel<<<512, 256, 0, s2>>>(x, n_elem, N);
    hist_kernel<<<(E + 255) / 256, 256, 0, s2>>>(dst, E);
    int nscan = (N + 256) / 256;
    scan1_kernel<<<nscan, 256, 0, s2>>>(N);
    scan2_kernel<<<1, 256, 0, s2>>>(nscan);
    scan3_kernel<<<nscan, 256, 0, s2>>>(N, E);
    fill_kernel<<<(E + 255) / 256, 256, 0, s2>>>(src, dst, E);
    cudaEventRecord(ev1, s2);

    // ----- branch B: gemm0 (raw x @ W0, fp16) -----
    int gblocks = (N + 127) / 128;
    gemm_kernel<<<gblocks, 256, gemm_smem>>>(x, W0, nullptr, 0, hs, N);

    // join
    cudaStreamWaitEvent(0, ev1, 0);

    int ablocks = (N + 7) / 8;
    agg_kernel<<<ablocks, 256>>>(hs, acc0, rowptr, adj, N);
    gemm_kernel<<<gblocks, 256, gemm_smem>>>(acc0, W1, cb0, 1, hs, N);
    agg_head_kernel<<<ablocks, 256>>>(hs, cb1, lW0, lb0, lW1, lb1, out, rowptr, adj, N);
}

// round 5
// speedup vs baseline: 2.0212x; 2.0212x over previous
#include <cuda_runtime.h>
#include <cuda_fp16.h>
#include <math.h>

// ---------------- scratch (no allocation allowed) ----------------
__device__ __half g_hs[5000000];   // 50000 x 100, fp16 (pre-scaled by dinv of own row)
__device__ float  g_acc[5000000];  // fp32 aggregate buffer (reused across layers)
__device__ float  g_dinv[50048];
__device__ int    g_cnt[50048];
__device__ int    g_rowptr[50049];
__device__ int    g_off[50049];
__device__ int    g_adj[800064];
__device__ int    g_bsum[256];
__device__ float  g_partials[512];
__device__ float  g_norm2;

// ---------------- prep: zero counters + ||x||^2 partial sums ----------------
__global__ void prep_kernel(const float* __restrict__ x, long n, int N) {
    int gs = gridDim.x * blockDim.x;
    for (int i = blockIdx.x * blockDim.x + threadIdx.x; i < N; i += gs) g_cnt[i] = 0;
    float s = 0.f;
    for (long i = (long)blockIdx.x * blockDim.x + threadIdx.x; i < n; i += gs) {
        float v = x[i];
        s += v * v;
    }
    __shared__ float sm[256];
    sm[threadIdx.x] = s;
    __syncthreads();
    for (int o = 128; o > 0; o >>= 1) {
        if (threadIdx.x < o) sm[threadIdx.x] += sm[threadIdx.x + o];
        __syncthreads();
    }
    if (threadIdx.x == 0) g_partials[blockIdx.x] = sm[0];
}

__global__ void hist_kernel(const int* __restrict__ dst, int E) {
    int i = blockIdx.x * blockDim.x + threadIdx.x;
    if (i < E) atomicAdd(&g_cnt[dst[i]], 1);
}

// dinv from degrees + finalize norm2 (block 0)
__global__ void dinv_norm_kernel(int N) {
    if (blockIdx.x == 0) {
        __shared__ float fm[256];
        fm[threadIdx.x] = g_partials[threadIdx.x] + g_partials[threadIdx.x + 256];
        __syncthreads();
        for (int o = 128; o > 0; o >>= 1) {
            if (threadIdx.x < o) fm[threadIdx.x] += fm[threadIdx.x + o];
            __syncthreads();
        }
        if (threadIdx.x == 0) g_norm2 = fm[0];
    }
    int i = blockIdx.x * 256 + threadIdx.x;
    if (i < N) g_dinv[i] = rsqrtf((float)(g_cnt[i] + 1));  // +1 self-loop
}

// ---------------- CSR build (scan + fill) ----------------
__global__ void scan1_kernel(int N) {
    __shared__ int sm[256];
    int node = blockIdx.x * 256 + threadIdx.x;
    int c = (node < N) ? g_cnt[node] : 0;
    sm[threadIdx.x] = c;
    __syncthreads();
    for (int o = 1; o < 256; o <<= 1) {
        int v = (threadIdx.x >= o) ? sm[threadIdx.x - o] : 0;
        __syncthreads();
        sm[threadIdx.x] += v;
        __syncthreads();
    }
    if (node <= N) g_rowptr[node] = sm[threadIdx.x] - c;
    if (threadIdx.x == 255) g_bsum[blockIdx.x] = sm[255];
}

__global__ void scan2_kernel(int nb) {
    __shared__ int sm[256];
    int c = (threadIdx.x < nb) ? g_bsum[threadIdx.x] : 0;
    sm[threadIdx.x] = c;
    __syncthreads();
    for (int o = 1; o < 256; o <<= 1) {
        int v = (threadIdx.x >= o) ? sm[threadIdx.x - o] : 0;
        __syncthreads();
        sm[threadIdx.x] += v;
        __syncthreads();
    }
    g_bsum[threadIdx.x] = sm[threadIdx.x] - c;
}

__global__ void scan3_kernel(int N, int E) {
    int node = blockIdx.x * 256 + threadIdx.x;
    if (node < N) {
        int r = g_rowptr[node] + g_bsum[blockIdx.x];
        g_rowptr[node] = r;
        g_off[node] = r;
    } else if (node == N) {
        g_rowptr[N] = E;
    }
}

__global__ void fill_kernel(const int* __restrict__ src, const int* __restrict__ dst, int E) {
    int i = blockIdx.x * blockDim.x + threadIdx.x;
    if (i < E) {
        int pos = atomicAdd(&g_off[dst[i]], 1);
        g_adj[pos] = src[i];
    }
}

// ---------------- GEMM: hs = fp16( dinv[row] * ((inscale(row)*X + bin) @ W) ) ----------------
// use_inscale: input row transform v = (dinv[row]*rsqrt(norm2))*X + bin (layer 1)
// 128 rows/block, 256 threads: (tx: 25-col group, ty: rows ty & ty+64)  [R2-proven config]
__global__ void __launch_bounds__(256)
gemm_kernel(const float* __restrict__ X, const float* __restrict__ W,
            const float* __restrict__ bin, int use_inscale,
            __half* __restrict__ hs, int N) {
    extern __shared__ float smem[];
    float* sW = smem;          // 10000 floats
    float* sX = smem + 10000;  // 128*100 = 12800 floats
    int tid = threadIdx.x;
    int row0 = blockIdx.x * 128;

    float nminv = use_inscale ? rsqrtf(g_norm2) : 1.0f;

    for (int i = tid; i < 2500; i += 256)
        ((float4*)sW)[i] = __ldg((const float4*)W + i);
    for (int i = tid; i < 3200; i += 256) {
        int r = i / 25, c = i - r * 25;
        int gr = row0 + r;
        float4 v = make_float4(0.f, 0.f, 0.f, 0.f);
        if (gr < N) {
            v = __ldg((const float4*)(X + (size_t)gr * 100) + c);
            if (use_inscale) {
                float s = g_dinv[gr] * nminv;
                float4 b = __ldg((const float4*)bin + c);
                v.x = v.x * s + b.x; v.y = v.y * s + b.y;
                v.z = v.z * s + b.z; v.w = v.w * s + b.w;
            }
        }
        *((float4*)(sX + r * 100) + c) = v;
    }
    __syncthreads();

    int tx = tid & 3, ty = tid >> 2;
    float a0[25], a1[25];
#pragma unroll
    for (int c = 0; c < 25; c++) { a0[c] = 0.f; a1[c] = 0.f; }
    const float* x0p = sX + ty * 100;
    const float* x1p = sX + (ty + 64) * 100;
    const float* wcol = sW + tx * 25;
#pragma unroll 2
    for (int k = 0; k < 100; k++) {
        float x0 = x0p[k];
        float x1 = x1p[k];
        const float* wr = wcol + k * 100;
#pragma unroll
        for (int c = 0; c < 25; c++) {
            float w = wr[c];
            a0[c] += x0 * w;
            a1[c] += x1 * w;
        }
    }

    int gr0 = row0 + ty;
    int gr1 = row0 + ty + 64;
    if (gr0 < N) {
        float s = g_dinv[gr0];
        __half* p = hs + (size_t)gr0 * 100 + tx * 25;
#pragma unroll
        for (int c = 0; c < 25; c++) p[c] = __float2half_rn(a0[c] * s);
    }
    if (gr1 < N) {
        float s = g_dinv[gr1];
        __half* p = hs + (size_t)gr1 * 100 + tx * 25;
#pragma unroll
        for (int c = 0; c < 25; c++) p[c] = __float2half_rn(a1[c] * s);
    }
}

// ---------------- CSR agg: acc[i] = hs[i] + sum_{j in adj[i]} hs[j]  (fp32 accum) ----------------
// one warp per node; lanes 0..24 own 4 cols (uint2 = 4 halves)  [R2-proven loop, fp16 payload]
__global__ void __launch_bounds__(256)
agg_kernel(const __half* __restrict__ hs, float* __restrict__ acc,
           const int* __restrict__ rowptr, const int* __restrict__ adj, int N) {
    int node = (blockIdx.x * 256 + threadIdx.x) >> 5;
    int lane = threadIdx.x & 31;
    if (node >= N) return;
    bool act = lane < 25;

    float4 sum = make_float4(0.f, 0.f, 0.f, 0.f);
    if (act) {
        uint2 raw = __ldg((const uint2*)(hs + (size_t)node * 100) + lane);
        float2 f0 = __half22float2(*(const __half2*)&raw.x);
        float2 f1 = __half22float2(*(const __half2*)&raw.y);
        sum.x = f0.x; sum.y = f0.y; sum.z = f1.x; sum.w = f1.y;
    }

    int beg = rowptr[node];
    int end = rowptr[node + 1];
    for (int base = beg; base < end; base += 32) {
        int idx = base + lane;
        int my = (idx < end) ? __ldg(adj + idx) : 0;
        int cnt = min(32, end - base);
#pragma unroll 4
        for (int j = 0; j < cnt; j++) {
            int s = __shfl_sync(0xffffffffu, my, j);
            if (act) {
                uint2 raw = __ldg((const uint2*)(hs + (size_t)s * 100) + lane);
                float2 f0 = __half22float2(*(const __half2*)&raw.x);
                float2 f1 = __half22float2(*(const __half2*)&raw.y);
                sum.x += f0.x; sum.y += f0.y; sum.z += f1.x; sum.w += f1.y;
            }
        }
    }
    if (act)
        *((float4*)(acc + (size_t)node * 100) + lane) = sum;
}

// ---------------- MLP head: out[i] = relu((dinv_i*acc + cb1) @ W0 + b0) @ W1 + b1 ----------------
__global__ void head_kernel(const float* __restrict__ acc, const float* __restrict__ bconv,
                            const float* __restrict__ W0, const float* __restrict__ b0,
                            const float* __restrict__ W1, const float* __restrict__ b1,
                            float* __restrict__ out, int N) {
    __shared__ float xs[64 * 101];
    __shared__ float w0s[1000];
    __shared__ float w1s[10];
    __shared__ float b0s[10];
    __shared__ float bcs[100];
    int tid = threadIdx.x;
    int base = blockIdx.x * 64;

    for (int i = tid; i < 1000; i += 128) w0s[i] = W0[i];
    if (tid < 10) { w1s[tid] = W1[tid]; b0s[tid] = b0[tid]; }
    if (tid < 100) bcs[tid] = bconv[tid];
    __syncthreads();

    for (int i = tid; i < 6400; i += 128) {
        int r = i / 100, k = i - r * 100;
        int g = base + r;
        xs[r * 101 + k] = (g < N) ? (g_dinv[g] * acc[(size_t)g * 100 + k] + bcs[k]) : 0.f;
    }
    __syncthreads();

    if (tid < 64) {
        int g = base + tid;
        if (g < N) {
            float y[10];
#pragma unroll
            for (int j = 0; j < 10; j++) y[j] = b0s[j];
            const float* xr = xs + tid * 101;
            for (int k = 0; k < 100; k++) {
                float xv = xr[k];
#pragma unroll
                for (int j = 0; j < 10; j++) y[j] += xv * w0s[k * 10 + j];
            }
            float o = b1[0];
#pragma unroll
            for (int j = 0; j < 10; j++) o += fmaxf(y[j], 0.f) * w1s[j];
            out[g] = o;
        }
    }
}

extern "C" void kernel_launch(void* const* d_in, const int* in_sizes, int n_in,
                              void* d_out, int out_size) {
    const float* x   = (const float*)d_in[0];
    const int*   ei  = (const int*)d_in[1];
    const float* W0  = (const float*)d_in[2];
    const float* cb0 = (const float*)d_in[3];
    const float* W1  = (const float*)d_in[4];
    const float* cb1 = (const float*)d_in[5];
    const float* lW0 = (const float*)d_in[6];
    const float* lb0 = (const float*)d_in[7];
    const float* lW1 = (const float*)d_in[8];
    const float* lb1 = (const float*)d_in[9];
    float* out = (float*)d_out;

    int N = in_sizes[0] / 100;
    int E = in_sizes[1] / 2;
    const int* src = ei;
    const int* dst = ei + E;

    size_t gemm_smem = (10000 + 12800) * sizeof(float);  // 91.2 KB -> 2 blocks/SM
    cudaFuncSetAttribute(gemm_kernel,
                         cudaFuncAttributeMaxDynamicSharedMemorySize, (int)gemm_smem);

    __half* hs;
    float* acc;
    int *rowptr, *adj;
    cudaGetSymbolAddress((void**)&hs, g_hs);
    cudaGetSymbolAddress((void**)&acc, g_acc);
    cudaGetSymbolAddress((void**)&rowptr, g_rowptr);
    cudaGetSymbolAddress((void**)&adj, g_adj);

    // phase 0 (serial): degrees + norm -> dinv  (gemm0 epilogue needs dinv)
    long n_elem = (long)N * 100;
    prep_kernel<<<512, 256>>>(x, n_elem, N);
    hist_kernel<<<(E + 255) / 256, 256>>>(dst, E);
    dinv_norm_kernel<<<(N + 255) / 256, 256>>>(N);

    // fork: branch A (CSR scan+fill) on s2  ||  branch B (gemm0) on default
    cudaStream_t s2;
    cudaStreamCreateWithFlags(&s2, cudaStreamNonBlocking);
    cudaEvent_t ev0, ev1;
    cudaEventCreateWithFlags(&ev0, cudaEventDisableTiming);
    cudaEventCreateWithFlags(&ev1, cudaEventDisableTiming);

    cudaEventRecord(ev0, 0);
    cudaStreamWaitEvent(s2, ev0, 0);

    int nscan = (N + 256) / 256;
    scan1_kernel<<<nscan, 256, 0, s2>>>(N);
    scan2_kernel<<<1, 256, 0, s2>>>(nscan);
    scan3_kernel<<<nscan, 256, 0, s2>>>(N, E);
    fill_kernel<<<(E + 255) / 256, 256, 0, s2>>>(src, dst, E);
    cudaEventRecord(ev1, s2);

    int gblocks = (N + 127) / 128;
    gemm_kernel<<<gblocks, 256, gemm_smem>>>(x, W0, nullptr, 0, hs, N);

    cudaStreamWaitEvent(0, ev1, 0);  // join

    int ablocks = (N + 7) / 8;  // 8 warps/block, warp per node
    agg_kernel<<<ablocks, 256>>>(hs, acc, rowptr, adj, N);
    gemm_kernel<<<gblocks, 256, gemm_smem>>>(acc, W1, cb0, 1, hs, N);
    agg_kernel<<<ablocks, 256>>>(hs, acc, rowptr, adj, N);
    head_kernel<<<(N + 63) / 64, 128>>>(acc, cb1, lW0, lb0, lW1, lb1, out, N);
}